// round 15
// baseline (speedup 1.0000x reference)
#include <cuda_runtime.h>
#include <cuda_fp16.h>
#include <cstdint>

#define B_DIM  2
#define N_SEQ  1024
#define DIMX   1024
#define HEADS  16
#define DH     64
#define INNER  1024
#define MAXPOS 512

// ------------------------- device scratch (no allocs) -----------------------
__device__ __align__(16) __half g_xf[(size_t)B_DIM*N_SEQ*DIMX];
__device__ __align__(16) __half g_wph[(size_t)3*DIMX*INNER];   // [Wq|Wkv]^T hi only
__device__ __align__(16) __half g_woh[(size_t)INNER*DIMX];
__device__ __align__(16) __half g_wol[(size_t)INNER*DIMX];
__device__ __align__(16) __half g_of[(size_t)B_DIM*N_SEQ*INNER];
// attention operands all single fp16; q pre-scaled by 0.125*log2e
__device__ __align__(16) __half g_qf[(size_t)B_DIM*HEADS*N_SEQ*DH];
__device__ __align__(16) __half g_kf[(size_t)B_DIM*HEADS*N_SEQ*DH];
__device__ __align__(16) __half g_vf[(size_t)B_DIM*HEADS*N_SEQ*DH];
__device__ __align__(16) __half g_relf[(size_t)(2*MAXPOS+1)*DH];

// ------------------------------- helpers ------------------------------------
__device__ __forceinline__ uint32_t smem_u32(const void* p) {
    uint32_t a;
    asm("{ .reg .u64 t; cvta.to.shared.u64 t, %1; cvt.u32.u64 %0, t; }"
        : "=r"(a) : "l"(p));
    return a;
}
__device__ __forceinline__ void cp16(uint32_t saddr, const void* gaddr) {
    asm volatile("cp.async.cg.shared.global [%0], [%1], 16;"
                 :: "r"(saddr), "l"(gaddr) : "memory");
}
__device__ __forceinline__ void ldm_x4(uint32_t a, uint32_t& r0, uint32_t& r1,
                                       uint32_t& r2, uint32_t& r3) {
    asm volatile("ldmatrix.sync.aligned.m8n8.x4.shared.b16 {%0,%1,%2,%3}, [%4];"
                 : "=r"(r0), "=r"(r1), "=r"(r2), "=r"(r3) : "r"(a));
}
__device__ __forceinline__ void ldm_x4t(uint32_t a, uint32_t& r0, uint32_t& r1,
                                        uint32_t& r2, uint32_t& r3) {
    asm volatile("ldmatrix.sync.aligned.m8n8.x4.trans.shared.b16 {%0,%1,%2,%3}, [%4];"
                 : "=r"(r0), "=r"(r1), "=r"(r2), "=r"(r3) : "r"(a));
}
__device__ __forceinline__ void mma16816h(float* c, const uint32_t* a,
                                          uint32_t b0, uint32_t b1) {
    asm volatile(
        "mma.sync.aligned.m16n8k16.row.col.f32.f16.f16.f32 "
        "{%0,%1,%2,%3}, {%4,%5,%6,%7}, {%8,%9}, {%0,%1,%2,%3};"
        : "+f"(c[0]), "+f"(c[1]), "+f"(c[2]), "+f"(c[3])
        : "r"(a[0]), "r"(a[1]), "r"(a[2]), "r"(a[3]), "r"(b0), "r"(b1));
}
__device__ __forceinline__ uint32_t sw128(uint32_t off) {
    return off ^ ((off >> 3) & 0x70);
}
__device__ __forceinline__ uint32_t pack_h2(float a, float b) {
    __half2 h = __floats2half2_rn(a, b);
    return *(uint32_t*)&h;
}

// ------------------- fused conversion kernel (one launch) -------------------
#define NX4 (B_DIM * N_SEQ * DIMX / 4)          // 524288
#define NR4 ((2 * MAXPOS + 1) * DH / 4)         // 16400
#define NCONV_BLK ((NX4 + NR4 + 255) / 256)     // 2113

__global__ __launch_bounds__(256) void convert_all(const float* __restrict__ x,
                                                   const float* __restrict__ rel,
                                                   const float* __restrict__ Wq,
                                                   const float* __restrict__ Wkv,
                                                   const float* __restrict__ Wo)
{
    const int bid = blockIdx.x;
    if (bid >= 4096) {
        int i = (bid - 4096) * 256 + threadIdx.x;
        if (i >= NX4 + NR4) return;
        if (i < NX4) {
            float4 v = ((const float4*)x)[i];
            ((uint32_t*)g_xf)[2*i]   = pack_h2(v.x, v.y);
            ((uint32_t*)g_xf)[2*i+1] = pack_h2(v.z, v.w);
        } else {
            int j = i - NX4;
            float4 v = ((const float4*)rel)[j];
            ((uint32_t*)g_relf)[2*j]   = pack_h2(v.x, v.y);
            ((uint32_t*)g_relf)[2*j+1] = pack_h2(v.z, v.w);
        }
        return;
    }
    __shared__ float t[32][33];
    const float* W; __half *th, *tl;
    int N, kt, ntile, rowoff;
    bool wantlo;
    if (bid < 1024)      { W = Wq;  N = 1024; kt = bid >> 5; ntile = bid & 31;
                           th = g_wph; tl = nullptr; rowoff = 0; wantlo = false; }
    else if (bid < 3072) { int l = bid - 1024; W = Wkv; N = 2048;
                           kt = l >> 6; ntile = l & 63;
                           th = g_wph; tl = nullptr; rowoff = 1024; wantlo = false; }
    else                 { int l = bid - 3072; W = Wo; N = 1024;
                           kt = l >> 5; ntile = l & 31;
                           th = g_woh; tl = g_wol; rowoff = 0; wantlo = true; }
    const int n0 = ntile * 32, k0 = kt * 32;
    const int tx = threadIdx.x & 31, ty = threadIdx.x >> 5;
#pragma unroll
    for (int r = 0; r < 4; r++)
        t[ty + 8*r][tx] = W[(size_t)(k0 + ty + 8*r) * N + n0 + tx];
    __syncthreads();
#pragma unroll
    for (int r = 0; r < 4; r++) {
        float v = t[tx][ty + 8*r];
        __half h = __float2half_rn(v);
        size_t o = (size_t)(rowoff + n0 + ty + 8*r) * 1024 + k0 + tx;
        th[o] = h;
        if (wantlo) tl[o] = __float2half_rn(v - __half2float(h));
    }
}

// ------------------------- fp16 GEMM (mma.sync) -----------------------------
// Tile 128x64, 128 threads = 4 warps (2x2), BK=64, SW128, 2-stage pipeline.
// mode 0 : 1-pass (A*Bh) — q/k/v stored single fp16 (Bl below storage noise).
// mode 2 : 2-pass (A*Bh + A*Bl) + bias -> fp32 out.
#define BK 64
#define A_TILE_B 16384            // 128 rows * 128 B
#define B_TILE_B 8192             // 64 rows * 128 B
#define STAGE_B (A_TILE_B + 2 * B_TILE_B)   // 32768
#define NSTAGE 2

__global__ __launch_bounds__(128, 3) void gemm_mma(int mode,
                                                   const float* __restrict__ bias,
                                                   float* __restrict__ outp)
{
    extern __shared__ __align__(128) char smem[];
    const uint32_t sb = smem_u32(smem);
    const int tid = threadIdx.x;
    const int wid = tid >> 5, lane = tid & 31;
    const int warp_m = wid & 1, warp_n = wid >> 1;   // 2 x 2
    const int m0 = blockIdx.y * 128, n0 = blockIdx.x * 64;
    const bool lite = (mode == 0);

    const __half *A, *Bh, *Bl;
    if (mode == 0) { A = g_xf; Bh = g_wph; Bl = nullptr; }
    else           { A = g_of; Bh = g_woh; Bl = g_wol; }

    float acc[4][4][4];
#pragma unroll
    for (int i = 0; i < 4; i++)
#pragma unroll
        for (int j = 0; j < 4; j++)
#pragma unroll
            for (int t = 0; t < 4; t++) acc[i][j][t] = 0.f;

    const int nkt = DIMX / BK;     // 16

    auto issue_stage = [&](int kt) {
        const int k0 = kt * BK;
        const uint32_t st = sb + (kt & 1) * STAGE_B;
#pragma unroll
        for (int i = 0; i < 8; i++) {
            int id = tid + i * 128;
            int r = id >> 3, cc = id & 7;
            cp16(st + sw128(r * 128 + cc * 16),
                 A + (size_t)(m0 + r) * DIMX + k0 + cc * 8);
        }
#pragma unroll
        for (int i = 0; i < 4; i++) {
            int id = tid + i * 128;
            int r = id >> 3, cc = id & 7;
            uint32_t sw = sw128(r * 128 + cc * 16);
            size_t g = (size_t)(n0 + r) * DIMX + k0 + cc * 8;
            cp16(st + A_TILE_B + sw, Bh + g);
            if (!lite) cp16(st + A_TILE_B + B_TILE_B + sw, Bl + g);
        }
        asm volatile("cp.async.commit_group;" ::: "memory");
    };

    issue_stage(0);

    const int lr = lane & 15;
    const int lcb = (lane >> 4) * 16;

    for (int kt = 0; kt < nkt; kt++) {
        if (kt + 1 < nkt) {
            issue_stage(kt + 1);
            asm volatile("cp.async.wait_group 1;" ::: "memory");
        } else {
            asm volatile("cp.async.wait_group 0;" ::: "memory");
        }
        __syncthreads();

        const uint32_t st = sb + (kt & 1) * STAGE_B;

#pragma unroll
        for (int ks = 0; ks < 4; ks++) {
            const uint32_t koffb = ks * 32 + lcb;
            uint32_t ah[4][4], bh[2][4], bl[2][4];
#pragma unroll
            for (int mt = 0; mt < 4; mt++) {
                uint32_t off = sw128((warp_m * 64 + mt * 16 + lr) * 128 + koffb);
                ldm_x4(st + off, ah[mt][0], ah[mt][1], ah[mt][2], ah[mt][3]);
            }
#pragma unroll
            for (int p = 0; p < 2; p++) {
                uint32_t off = sw128((warp_n * 32 + p * 16 + lr) * 128 + koffb);
                ldm_x4(st + A_TILE_B + off,
                       bh[p][0], bh[p][1], bh[p][2], bh[p][3]);
                if (!lite)
                    ldm_x4(st + A_TILE_B + B_TILE_B + off,
                           bl[p][0], bl[p][1], bl[p][2], bl[p][3]);
            }
#pragma unroll
            for (int mt = 0; mt < 4; mt++)
#pragma unroll
                for (int nt = 0; nt < 4; nt++) {
                    const int p = nt >> 1, s = nt & 1;
                    mma16816h(acc[mt][nt], ah[mt], bh[p][s], bh[p][s + 2]);
                    if (!lite)
                        mma16816h(acc[mt][nt], ah[mt], bl[p][s], bl[p][s + 2]);
                }
        }
        __syncthreads();
    }

    const float qscale = 0.125f * 1.4426950408889634f;
#pragma unroll
    for (int mt = 0; mt < 4; mt++) {
#pragma unroll
        for (int half = 0; half < 2; half++) {
            const int m = m0 + warp_m * 64 + mt * 16 + (lane >> 2) + half * 8;
#pragma unroll
            for (int nt = 0; nt < 4; nt++) {
                const int c = n0 + warp_n * 32 + nt * 8 + 2 * (lane & 3);
                float v0 = acc[mt][nt][half * 2 + 0];
                float v1 = acc[mt][nt][half * 2 + 1];
                if (mode != 0) {
                    float2 o = {v0 + bias[c], v1 + bias[c + 1]};
                    *(float2*)&outp[(size_t)m * DIMX + c] = o;
                } else {
                    const int bb = m >> 10, ii = m & 1023;
                    int col0 = c;
                    __half* dst;
                    float sc = 1.f;
                    if (c < INNER) { dst = g_qf; sc = qscale; }
                    else if (c < 2 * INNER) { dst = g_kf; col0 = c - INNER; }
                    else { dst = g_vf; col0 = c - 2 * INNER; }
                    const int hh = col0 >> 6, dd = col0 & 63;
                    size_t o = (((size_t)bb * HEADS + hh) * N_SEQ + ii) * DH + dd;
                    *(uint32_t*)&dst[o] = pack_h2(v0 * sc, v1 * sc);
                }
            }
        }
    }
}

// ---------------------------------------------------------------------------
// Tensor-core flash attention: ALL operands single fp16 (Q, K, V, rel, P),
// fp16 S2 ring, exp2 softmax, tri-state clip-skip.
// Round-15: occupancy 4 (slim single-pass kernel fits the 128-reg cap;
// grid 512 <= 4*148 slots -> single wave, 16 warps/SM).
// ---------------------------------------------------------------------------
#define A_Q  0
#define A_K  8192
#define A_V  16384
#define A_R  24576
#define A_S2 32768
#define S2S  132
#define ATT_SMEM (A_S2 + 64 * S2S * 2)   // 49664

__global__ __launch_bounds__(128, 4) void attn_mma(void)
{
    extern __shared__ __align__(128) char smem[];
    const uint32_t sb = smem_u32(smem);
    __half* s2h = (__half*)(smem + A_S2);

    const int tid  = threadIdx.x;
    const int lane = tid & 31, warp = tid >> 5;
    const int wbase = warp * 16;
    const int i0 = blockIdx.x * 64;
    const int h  = blockIdx.y;
    const int b  = blockIdx.z;
    const size_t hb = ((size_t)b * HEADS + h) * N_SEQ * DH;

    // ---- load Q (single plane) ----
#pragma unroll
    for (int i = 0; i < 4; i++) {
        int id = tid + i * 128;
        int r = id >> 3, c = id & 7;
        uint32_t d = sw128(r * 128 + c * 16);
        cp16(sb + A_Q + d, g_qf + hb + (size_t)(i0 + r) * DH + c * 8);
    }
    asm volatile("cp.async.commit_group;" ::: "memory");
    asm volatile("cp.async.wait_group 0;" ::: "memory");
    __syncthreads();

    uint32_t qa[4][4];
#pragma unroll
    for (int ks = 0; ks < 4; ks++) {
        uint32_t off = sw128((wbase + (lane & 15)) * 128 + ks * 32 + (lane >> 4) * 16);
        ldm_x4(sb + A_Q + off, qa[ks][0], qa[ks][1], qa[ks][2], qa[ks][3]);
    }

    auto stage_rel = [&](int Dbase) {
#pragma unroll
        for (int i = 0; i < 4; i++) {
            int id = tid + i * 128;
            int r = id >> 3, c = id & 7;
            int dist = min(max(Dbase + r, -MAXPOS), MAXPOS) + MAXPOS;
            uint32_t d = sw128(r * 128 + c * 16);
            cp16(sb + A_R + d, g_relf + (size_t)dist * DH + c * 8);
        }
    };

    auto s2_group = [&](int baseSlot) {
        float s2[8][4];
#pragma unroll
        for (int nt = 0; nt < 8; nt++)
#pragma unroll
            for (int e = 0; e < 4; e++) s2[nt][e] = 0.f;
#pragma unroll
        for (int ks = 0; ks < 4; ks++) {
            uint32_t rb[4][4];
#pragma unroll
            for (int g = 0; g < 4; g++) {
                uint32_t off = sw128((g * 16 + (lane & 15)) * 128
                                     + ks * 32 + (lane >> 4) * 16);
                ldm_x4(sb + A_R + off, rb[g][0], rb[g][1], rb[g][2], rb[g][3]);
            }
#pragma unroll
            for (int nt = 0; nt < 8; nt++) {
                const int p = nt >> 1, s_ = nt & 1;
                mma16816h(s2[nt], qa[ks], rb[p][s_], rb[p][s_ + 2]);
            }
        }
        const int rl0 = wbase + (lane >> 2);
#pragma unroll
        for (int nt = 0; nt < 8; nt++) {
            const int col = baseSlot + nt * 8 + 2 * (lane & 3);
            *(uint32_t*)&s2h[rl0 * S2S + col]       = pack_h2(s2[nt][0], s2[nt][1]);
            *(uint32_t*)&s2h[(rl0 + 8) * S2S + col] = pack_h2(s2[nt][2], s2[nt][3]);
        }
    };

    // clip state per slot-group parity: 0=varying, 1=low-clip const, 2=high-clip const
    int cst[2];
    cst[0] = 0;
    cst[1] = (i0 + 1 >= MAXPOS) ? 2 : 0;

    // ---- pre-group: slots 64..127 = dists [i0+1, i0+64] ----
    stage_rel(i0 + 1);
    asm volatile("cp.async.commit_group;" ::: "memory");
    asm volatile("cp.async.wait_group 0;" ::: "memory");
    __syncthreads();
    s2_group(64);

    float o[8][4];
#pragma unroll
    for (int nt = 0; nt < 8; nt++)
#pragma unroll
        for (int e = 0; e < 4; e++) o[nt][e] = 0.f;
    float m2[2] = {-1e30f, -1e30f}, l2[2] = {0.f, 0.f};

    for (int jt = 0; jt < 16; jt++) {
        const int j0 = jt * 64;
        __syncthreads();   // prior tile's SMEM reads complete

        // group A: K + (maybe) new rel rows
#pragma unroll
        for (int i = 0; i < 4; i++) {
            int id = tid + i * 128;
            int r = id >> 3, c = id & 7;
            uint32_t d = sw128(r * 128 + c * 16);
            cp16(sb + A_K + d, g_kf + hb + (size_t)(j0 + r) * DH + c * 8);
        }
        const int Dbase = i0 - j0 - 63;
        int cc = 0;
        if (Dbase + 63 <= -MAXPOS) cc = 1;
        else if (Dbase >= MAXPOS)  cc = 2;
        const bool skip = (cc != 0) && (cst[jt & 1] == cc);
        if (!skip) stage_rel(Dbase);
        cst[jt & 1] = cc;
        asm volatile("cp.async.commit_group;" ::: "memory");
        // group B: V
#pragma unroll
        for (int i = 0; i < 4; i++) {
            int id = tid + i * 128;
            int r = id >> 3, c = id & 7;
            uint32_t d = sw128(r * 128 + c * 16);
            cp16(sb + A_V + d, g_vf + hb + (size_t)(j0 + r) * DH + c * 8);
        }
        asm volatile("cp.async.commit_group;" ::: "memory");

        asm volatile("cp.async.wait_group 1;" ::: "memory");
        __syncthreads();

        // ---- new S2 columns (64) ----
        if (!skip) s2_group((jt & 1) ? 64 : 0);
        __syncwarp();

        // ---- S1 = Q @ K^T (64x64), single pass ----
        float s[8][4];
#pragma unroll
        for (int nt = 0; nt < 8; nt++)
#pragma unroll
            for (int e = 0; e < 4; e++) s[nt][e] = 0.f;
#pragma unroll
        for (int ks = 0; ks < 4; ks++) {
            uint32_t kb[4][4];
#pragma unroll
            for (int g = 0; g < 4; g++) {
                uint32_t off = sw128((g * 16 + (lane & 15)) * 128
                                     + ks * 32 + (lane >> 4) * 16);
                ldm_x4(sb + A_K + off, kb[g][0], kb[g][1], kb[g][2], kb[g][3]);
            }
#pragma unroll
            for (int nt = 0; nt < 8; nt++) {
                const int p = nt >> 1, s_ = nt & 1;
                mma16816h(s[nt], qa[ks], kb[p][s_], kb[p][s_ + 2]);
            }
        }

        // ---- gather rel bias from ring, online softmax (base-2 domain) ----
        const int rl0 = wbase + (lane >> 2);
#pragma unroll
        for (int nt = 0; nt < 8; nt++)
#pragma unroll
            for (int e = 0; e < 4; e++) {
                const int rr = rl0 + 8 * (e >> 1);
                const int jj = nt * 8 + 2 * (lane & 3) + (e & 1);
                const int slot = (rr - jj + 63 - j0) & 127;
                s[nt][e] += __half2float(s2h[rr * S2S + slot]);
            }

        float mx[2] = {-1e30f, -1e30f};
#pragma unroll
        for (int nt = 0; nt < 8; nt++)
#pragma unroll
            for (int e = 0; e < 4; e++)
                mx[e >> 1] = fmaxf(mx[e >> 1], s[nt][e]);
#pragma unroll
        for (int h2 = 0; h2 < 2; h2++) {
            mx[h2] = fmaxf(mx[h2], __shfl_xor_sync(0xffffffffu, mx[h2], 1));
            mx[h2] = fmaxf(mx[h2], __shfl_xor_sync(0xffffffffu, mx[h2], 2));
        }
        float al2[2];
#pragma unroll
        for (int h2 = 0; h2 < 2; h2++) {
            float mnew = fmaxf(m2[h2], mx[h2]);
            al2[h2] = exp2f(m2[h2] - mnew);
            m2[h2] = mnew;
        }
        float sum[2] = {0.f, 0.f};
#pragma unroll
        for (int nt = 0; nt < 8; nt++)
#pragma unroll
            for (int e = 0; e < 4; e++) {
                float p = exp2f(s[nt][e] - m2[e >> 1]);
                s[nt][e] = p;
                sum[e >> 1] += p;
            }
#pragma unroll
        for (int h2 = 0; h2 < 2; h2++) {
            sum[h2] += __shfl_xor_sync(0xffffffffu, sum[h2], 1);
            sum[h2] += __shfl_xor_sync(0xffffffffu, sum[h2], 2);
            l2[h2] = l2[h2] * al2[h2] + sum[h2];
        }
#pragma unroll
        for (int nt = 0; nt < 8; nt++) {
            o[nt][0] *= al2[0]; o[nt][1] *= al2[0];
            o[nt][2] *= al2[1]; o[nt][3] *= al2[1];
        }

        // ---- P c-frag -> a-frag (single fp16) ----
        uint32_t pa[4][4];
#pragma unroll
        for (int ks = 0; ks < 4; ks++) {
            pa[ks][0] = pack_h2(s[2*ks][0],   s[2*ks][1]);
            pa[ks][1] = pack_h2(s[2*ks][2],   s[2*ks][3]);
            pa[ks][2] = pack_h2(s[2*ks+1][0], s[2*ks+1][1]);
            pa[ks][3] = pack_h2(s[2*ks+1][2], s[2*ks+1][3]);
        }

        asm volatile("cp.async.wait_group 0;" ::: "memory");
        __syncthreads();

        // ---- O += P @ V (single pass) ----
#pragma unroll
        for (int ks = 0; ks < 4; ks++) {
            uint32_t vb[4][4];
            const int jr = ks * 16 + (lane & 7) + ((lane >> 3) & 1) * 8;
#pragma unroll
            for (int dp = 0; dp < 4; dp++) {
                uint32_t off = sw128(jr * 128 + dp * 32 + (lane >> 4) * 16);
                ldm_x4t(sb + A_V + off, vb[dp][0], vb[dp][1], vb[dp][2], vb[dp][3]);
            }
#pragma unroll
            for (int nt = 0; nt < 8; nt++) {
                const int dp = nt >> 1, s_ = (nt & 1) * 2;
                mma16816h(o[nt], pa[ks], vb[dp][s_], vb[dp][s_ + 1]);
            }
        }
    }

    // ---- epilogue: normalize -> single fp16 g_of ----
    const float inv0 = 1.f / l2[0], inv1 = 1.f / l2[1];
    const int row0 = i0 + wbase + (lane >> 2);
#pragma unroll
    for (int nt = 0; nt < 8; nt++) {
        const int d = nt * 8 + 2 * (lane & 3);
        size_t base0 = ((size_t)b * N_SEQ + row0) * INNER + h * DH + d;
        *(uint32_t*)&g_of[base0] = pack_h2(o[nt][0] * inv0, o[nt][1] * inv0);
        size_t base1 = ((size_t)b * N_SEQ + row0 + 8) * INNER + h * DH + d;
        *(uint32_t*)&g_of[base1] = pack_h2(o[nt][2] * inv1, o[nt][3] * inv1);
    }
}

// ---------------------------------------------------------------------------
extern "C" void kernel_launch(void* const* d_in, const int* in_sizes, int n_in,
                              void* d_out, int out_size)
{
    (void)in_sizes; (void)n_in; (void)out_size;
    const float* x   = (const float*)d_in[0];
    const float* Wq  = (const float*)d_in[1];
    const float* Wkv = (const float*)d_in[2];
    const float* Wo  = (const float*)d_in[3];
    const float* bo  = (const float*)d_in[4];
    const float* rel = (const float*)d_in[5];
    float* out = (float*)d_out;

    const int GEMM_SMEM = NSTAGE * STAGE_B;      // 65536
    cudaFuncSetAttribute(gemm_mma, cudaFuncAttributeMaxDynamicSharedMemorySize, GEMM_SMEM);
    cudaFuncSetAttribute(attn_mma, cudaFuncAttributeMaxDynamicSharedMemorySize, ATT_SMEM);

    // all fp32 -> fp16 conversions in one launch (no lo-planes for Wq/Wkv)
    convert_all<<<4096 + NCONV_BLK, 256>>>(x, rel, Wq, Wkv, Wo);

    // fused q/k/v projection: x @ [Wq|Wkv], single-pass
    gemm_mma<<<dim3(3 * INNER / 64, (B_DIM * N_SEQ) / 128), 128, GEMM_SMEM>>>(0, nullptr, nullptr);

    // fused attention (all-fp16, occ 4, single wave)
    attn_mma<<<dim3(16, HEADS, B_DIM), 128, ATT_SMEM>>>();

    // out = o @ Wo + bo (2-pass)
    gemm_mma<<<dim3(DIMX / 64, (B_DIM * N_SEQ) / 128), 128, GEMM_SMEM>>>(2, bo, out);
}

// round 16
// speedup vs baseline: 1.0356x; 1.0356x over previous
#include <cuda_runtime.h>
#include <cuda_fp16.h>
#include <cstdint>

#define B_DIM  2
#define N_SEQ  1024
#define DIMX   1024
#define HEADS  16
#define DH     64
#define INNER  1024
#define MAXPOS 512

// ------------------------- device scratch (no allocs) -----------------------
__device__ __align__(16) __half g_xf[(size_t)B_DIM*N_SEQ*DIMX];
__device__ __align__(16) __half g_wph[(size_t)3*DIMX*INNER];   // [Wq|Wkv]^T hi only
__device__ __align__(16) __half g_woh[(size_t)INNER*DIMX];
__device__ __align__(16) __half g_wol[(size_t)INNER*DIMX];
__device__ __align__(16) __half g_of[(size_t)B_DIM*N_SEQ*INNER];
// attention operands all single fp16; q pre-scaled by 0.125*log2e
__device__ __align__(16) __half g_qf[(size_t)B_DIM*HEADS*N_SEQ*DH];
__device__ __align__(16) __half g_kf[(size_t)B_DIM*HEADS*N_SEQ*DH];
__device__ __align__(16) __half g_vf[(size_t)B_DIM*HEADS*N_SEQ*DH];
__device__ __align__(16) __half g_relf[(size_t)(2*MAXPOS+1)*DH];

// ------------------------------- helpers ------------------------------------
__device__ __forceinline__ uint32_t smem_u32(const void* p) {
    uint32_t a;
    asm("{ .reg .u64 t; cvta.to.shared.u64 t, %1; cvt.u32.u64 %0, t; }"
        : "=r"(a) : "l"(p));
    return a;
}
__device__ __forceinline__ void cp16(uint32_t saddr, const void* gaddr) {
    asm volatile("cp.async.cg.shared.global [%0], [%1], 16;"
                 :: "r"(saddr), "l"(gaddr) : "memory");
}
__device__ __forceinline__ void ldm_x4(uint32_t a, uint32_t& r0, uint32_t& r1,
                                       uint32_t& r2, uint32_t& r3) {
    asm volatile("ldmatrix.sync.aligned.m8n8.x4.shared.b16 {%0,%1,%2,%3}, [%4];"
                 : "=r"(r0), "=r"(r1), "=r"(r2), "=r"(r3) : "r"(a));
}
__device__ __forceinline__ void ldm_x4t(uint32_t a, uint32_t& r0, uint32_t& r1,
                                        uint32_t& r2, uint32_t& r3) {
    asm volatile("ldmatrix.sync.aligned.m8n8.x4.trans.shared.b16 {%0,%1,%2,%3}, [%4];"
                 : "=r"(r0), "=r"(r1), "=r"(r2), "=r"(r3) : "r"(a));
}
__device__ __forceinline__ void mma16816h(float* c, const uint32_t* a,
                                          uint32_t b0, uint32_t b1) {
    asm volatile(
        "mma.sync.aligned.m16n8k16.row.col.f32.f16.f16.f32 "
        "{%0,%1,%2,%3}, {%4,%5,%6,%7}, {%8,%9}, {%0,%1,%2,%3};"
        : "+f"(c[0]), "+f"(c[1]), "+f"(c[2]), "+f"(c[3])
        : "r"(a[0]), "r"(a[1]), "r"(a[2]), "r"(a[3]), "r"(b0), "r"(b1));
}
__device__ __forceinline__ uint32_t sw128(uint32_t off) {
    return off ^ ((off >> 3) & 0x70);
}
__device__ __forceinline__ uint32_t pack_h2(float a, float b) {
    __half2 h = __floats2half2_rn(a, b);
    return *(uint32_t*)&h;
}

// ------------------- fused conversion kernel (one launch) -------------------
#define NX4 (B_DIM * N_SEQ * DIMX / 4)          // 524288
#define NR4 ((2 * MAXPOS + 1) * DH / 4)         // 16400
#define NCONV_BLK ((NX4 + NR4 + 255) / 256)     // 2113

__global__ __launch_bounds__(256) void convert_all(const float* __restrict__ x,
                                                   const float* __restrict__ rel,
                                                   const float* __restrict__ Wq,
                                                   const float* __restrict__ Wkv,
                                                   const float* __restrict__ Wo)
{
    const int bid = blockIdx.x;
    if (bid >= 4096) {
        int i = (bid - 4096) * 256 + threadIdx.x;
        if (i >= NX4 + NR4) return;
        if (i < NX4) {
            float4 v = ((const float4*)x)[i];
            ((uint32_t*)g_xf)[2*i]   = pack_h2(v.x, v.y);
            ((uint32_t*)g_xf)[2*i+1] = pack_h2(v.z, v.w);
        } else {
            int j = i - NX4;
            float4 v = ((const float4*)rel)[j];
            ((uint32_t*)g_relf)[2*j]   = pack_h2(v.x, v.y);
            ((uint32_t*)g_relf)[2*j+1] = pack_h2(v.z, v.w);
        }
        return;
    }
    __shared__ float t[32][33];
    const float* W; __half *th, *tl;
    int N, kt, ntile, rowoff;
    bool wantlo;
    if (bid < 1024)      { W = Wq;  N = 1024; kt = bid >> 5; ntile = bid & 31;
                           th = g_wph; tl = nullptr; rowoff = 0; wantlo = false; }
    else if (bid < 3072) { int l = bid - 1024; W = Wkv; N = 2048;
                           kt = l >> 6; ntile = l & 63;
                           th = g_wph; tl = nullptr; rowoff = 1024; wantlo = false; }
    else                 { int l = bid - 3072; W = Wo; N = 1024;
                           kt = l >> 5; ntile = l & 31;
                           th = g_woh; tl = g_wol; rowoff = 0; wantlo = true; }
    const int n0 = ntile * 32, k0 = kt * 32;
    const int tx = threadIdx.x & 31, ty = threadIdx.x >> 5;
#pragma unroll
    for (int r = 0; r < 4; r++)
        t[ty + 8*r][tx] = W[(size_t)(k0 + ty + 8*r) * N + n0 + tx];
    __syncthreads();
#pragma unroll
    for (int r = 0; r < 4; r++) {
        float v = t[tx][ty + 8*r];
        __half h = __float2half_rn(v);
        size_t o = (size_t)(rowoff + n0 + ty + 8*r) * 1024 + k0 + tx;
        th[o] = h;
        if (wantlo) tl[o] = __float2half_rn(v - __half2float(h));
    }
}

// ------------------------- fp16 GEMM (mma.sync) -----------------------------
// Tile 64x64, 128 threads = 4 warps (2x2), warp tile 32x32, BK=64, SW128,
// 2-stage pipeline, occ 4 (acc halved to 32 regs -> fits 128-reg cap).
// mode 0 : 1-pass (A*Bh). mode 2 : 2-pass + bias -> fp32 out.
// K-accumulation order identical to the 128x64 version -> bitwise-same result.
#define BK 64
#define A_TILE_B 8192             // 64 rows * 128 B
#define B_TILE_B 8192             // 64 rows * 128 B
#define STAGE_B (A_TILE_B + 2 * B_TILE_B)   // 24576
#define NSTAGE 2

__global__ __launch_bounds__(128, 4) void gemm_mma(int mode,
                                                   const float* __restrict__ bias,
                                                   float* __restrict__ outp)
{
    extern __shared__ __align__(128) char smem[];
    const uint32_t sb = smem_u32(smem);
    const int tid = threadIdx.x;
    const int wid = tid >> 5, lane = tid & 31;
    const int warp_m = wid & 1, warp_n = wid >> 1;   // 2 x 2
    const int m0 = blockIdx.y * 64, n0 = blockIdx.x * 64;
    const bool lite = (mode == 0);

    const __half *A, *Bh, *Bl;
    if (mode == 0) { A = g_xf; Bh = g_wph; Bl = nullptr; }
    else           { A = g_of; Bh = g_woh; Bl = g_wol; }

    float acc[2][4][4];
#pragma unroll
    for (int i = 0; i < 2; i++)
#pragma unroll
        for (int j = 0; j < 4; j++)
#pragma unroll
            for (int t = 0; t < 4; t++) acc[i][j][t] = 0.f;

    const int nkt = DIMX / BK;     // 16

    auto issue_stage = [&](int kt) {
        const int k0 = kt * BK;
        const uint32_t st = sb + (kt & 1) * STAGE_B;
        // A: 64 rows x 128 B = 512 chunks, 4 per thread
#pragma unroll
        for (int i = 0; i < 4; i++) {
            int id = tid + i * 128;
            int r = id >> 3, cc = id & 7;
            cp16(st + sw128(r * 128 + cc * 16),
                 A + (size_t)(m0 + r) * DIMX + k0 + cc * 8);
        }
        // Bh (+Bl): 64 rows x 128 B = 512 chunks each, 4 per thread
#pragma unroll
        for (int i = 0; i < 4; i++) {
            int id = tid + i * 128;
            int r = id >> 3, cc = id & 7;
            uint32_t sw = sw128(r * 128 + cc * 16);
            size_t g = (size_t)(n0 + r) * DIMX + k0 + cc * 8;
            cp16(st + A_TILE_B + sw, Bh + g);
            if (!lite) cp16(st + A_TILE_B + B_TILE_B + sw, Bl + g);
        }
        asm volatile("cp.async.commit_group;" ::: "memory");
    };

    issue_stage(0);

    const int lr = lane & 15;
    const int lcb = (lane >> 4) * 16;

    for (int kt = 0; kt < nkt; kt++) {
        if (kt + 1 < nkt) {
            issue_stage(kt + 1);
            asm volatile("cp.async.wait_group 1;" ::: "memory");
        } else {
            asm volatile("cp.async.wait_group 0;" ::: "memory");
        }
        __syncthreads();

        const uint32_t st = sb + (kt & 1) * STAGE_B;

#pragma unroll
        for (int ks = 0; ks < 4; ks++) {
            const uint32_t koffb = ks * 32 + lcb;
            uint32_t ah[2][4], bh[2][4], bl[2][4];
#pragma unroll
            for (int mt = 0; mt < 2; mt++) {
                uint32_t off = sw128((warp_m * 32 + mt * 16 + lr) * 128 + koffb);
                ldm_x4(st + off, ah[mt][0], ah[mt][1], ah[mt][2], ah[mt][3]);
            }
#pragma unroll
            for (int p = 0; p < 2; p++) {
                uint32_t off = sw128((warp_n * 32 + p * 16 + lr) * 128 + koffb);
                ldm_x4(st + A_TILE_B + off,
                       bh[p][0], bh[p][1], bh[p][2], bh[p][3]);
                if (!lite)
                    ldm_x4(st + A_TILE_B + B_TILE_B + off,
                           bl[p][0], bl[p][1], bl[p][2], bl[p][3]);
            }
#pragma unroll
            for (int mt = 0; mt < 2; mt++)
#pragma unroll
                for (int nt = 0; nt < 4; nt++) {
                    const int p = nt >> 1, s = nt & 1;
                    mma16816h(acc[mt][nt], ah[mt], bh[p][s], bh[p][s + 2]);
                    if (!lite)
                        mma16816h(acc[mt][nt], ah[mt], bl[p][s], bl[p][s + 2]);
                }
        }
        __syncthreads();
    }

    const float qscale = 0.125f * 1.4426950408889634f;
#pragma unroll
    for (int mt = 0; mt < 2; mt++) {
#pragma unroll
        for (int half = 0; half < 2; half++) {
            const int m = m0 + warp_m * 32 + mt * 16 + (lane >> 2) + half * 8;
#pragma unroll
            for (int nt = 0; nt < 4; nt++) {
                const int c = n0 + warp_n * 32 + nt * 8 + 2 * (lane & 3);
                float v0 = acc[mt][nt][half * 2 + 0];
                float v1 = acc[mt][nt][half * 2 + 1];
                if (mode != 0) {
                    float2 o = {v0 + bias[c], v1 + bias[c + 1]};
                    *(float2*)&outp[(size_t)m * DIMX + c] = o;
                } else {
                    const int bb = m >> 10, ii = m & 1023;
                    int col0 = c;
                    __half* dst;
                    float sc = 1.f;
                    if (c < INNER) { dst = g_qf; sc = qscale; }
                    else if (c < 2 * INNER) { dst = g_kf; col0 = c - INNER; }
                    else { dst = g_vf; col0 = c - 2 * INNER; }
                    const int hh = col0 >> 6, dd = col0 & 63;
                    size_t o = (((size_t)bb * HEADS + hh) * N_SEQ + ii) * DH + dd;
                    *(uint32_t*)&dst[o] = pack_h2(v0 * sc, v1 * sc);
                }
            }
        }
    }
}

// ---------------------------------------------------------------------------
// Tensor-core flash attention: ALL operands single fp16 (Q, K, V, rel, P),
// fp16 S2 ring, exp2 softmax, tri-state clip-skip, occ 3 (proven R14 config).
// ---------------------------------------------------------------------------
#define A_Q  0
#define A_K  8192
#define A_V  16384
#define A_R  24576
#define A_S2 32768
#define S2S  132
#define ATT_SMEM (A_S2 + 64 * S2S * 2)   // 49664

__global__ __launch_bounds__(128, 3) void attn_mma(void)
{
    extern __shared__ __align__(128) char smem[];
    const uint32_t sb = smem_u32(smem);
    __half* s2h = (__half*)(smem + A_S2);

    const int tid  = threadIdx.x;
    const int lane = tid & 31, warp = tid >> 5;
    const int wbase = warp * 16;
    const int i0 = blockIdx.x * 64;
    const int h  = blockIdx.y;
    const int b  = blockIdx.z;
    const size_t hb = ((size_t)b * HEADS + h) * N_SEQ * DH;

    // ---- load Q (single plane) ----
#pragma unroll
    for (int i = 0; i < 4; i++) {
        int id = tid + i * 128;
        int r = id >> 3, c = id & 7;
        uint32_t d = sw128(r * 128 + c * 16);
        cp16(sb + A_Q + d, g_qf + hb + (size_t)(i0 + r) * DH + c * 8);
    }
    asm volatile("cp.async.commit_group;" ::: "memory");
    asm volatile("cp.async.wait_group 0;" ::: "memory");
    __syncthreads();

    uint32_t qa[4][4];
#pragma unroll
    for (int ks = 0; ks < 4; ks++) {
        uint32_t off = sw128((wbase + (lane & 15)) * 128 + ks * 32 + (lane >> 4) * 16);
        ldm_x4(sb + A_Q + off, qa[ks][0], qa[ks][1], qa[ks][2], qa[ks][3]);
    }

    auto stage_rel = [&](int Dbase) {
#pragma unroll
        for (int i = 0; i < 4; i++) {
            int id = tid + i * 128;
            int r = id >> 3, c = id & 7;
            int dist = min(max(Dbase + r, -MAXPOS), MAXPOS) + MAXPOS;
            uint32_t d = sw128(r * 128 + c * 16);
            cp16(sb + A_R + d, g_relf + (size_t)dist * DH + c * 8);
        }
    };

    auto s2_group = [&](int baseSlot) {
        float s2[8][4];
#pragma unroll
        for (int nt = 0; nt < 8; nt++)
#pragma unroll
            for (int e = 0; e < 4; e++) s2[nt][e] = 0.f;
#pragma unroll
        for (int ks = 0; ks < 4; ks++) {
            uint32_t rb[4][4];
#pragma unroll
            for (int g = 0; g < 4; g++) {
                uint32_t off = sw128((g * 16 + (lane & 15)) * 128
                                     + ks * 32 + (lane >> 4) * 16);
                ldm_x4(sb + A_R + off, rb[g][0], rb[g][1], rb[g][2], rb[g][3]);
            }
#pragma unroll
            for (int nt = 0; nt < 8; nt++) {
                const int p = nt >> 1, s_ = nt & 1;
                mma16816h(s2[nt], qa[ks], rb[p][s_], rb[p][s_ + 2]);
            }
        }
        const int rl0 = wbase + (lane >> 2);
#pragma unroll
        for (int nt = 0; nt < 8; nt++) {
            const int col = baseSlot + nt * 8 + 2 * (lane & 3);
            *(uint32_t*)&s2h[rl0 * S2S + col]       = pack_h2(s2[nt][0], s2[nt][1]);
            *(uint32_t*)&s2h[(rl0 + 8) * S2S + col] = pack_h2(s2[nt][2], s2[nt][3]);
        }
    };

    // clip state per slot-group parity: 0=varying, 1=low-clip const, 2=high-clip const
    int cst[2];
    cst[0] = 0;
    cst[1] = (i0 + 1 >= MAXPOS) ? 2 : 0;

    // ---- pre-group: slots 64..127 = dists [i0+1, i0+64] ----
    stage_rel(i0 + 1);
    asm volatile("cp.async.commit_group;" ::: "memory");
    asm volatile("cp.async.wait_group 0;" ::: "memory");
    __syncthreads();
    s2_group(64);

    float o[8][4];
#pragma unroll
    for (int nt = 0; nt < 8; nt++)
#pragma unroll
        for (int e = 0; e < 4; e++) o[nt][e] = 0.f;
    float m2[2] = {-1e30f, -1e30f}, l2[2] = {0.f, 0.f};

    for (int jt = 0; jt < 16; jt++) {
        const int j0 = jt * 64;
        __syncthreads();   // prior tile's SMEM reads complete

        // group A: K + (maybe) new rel rows
#pragma unroll
        for (int i = 0; i < 4; i++) {
            int id = tid + i * 128;
            int r = id >> 3, c = id & 7;
            uint32_t d = sw128(r * 128 + c * 16);
            cp16(sb + A_K + d, g_kf + hb + (size_t)(j0 + r) * DH + c * 8);
        }
        const int Dbase = i0 - j0 - 63;
        int cc = 0;
        if (Dbase + 63 <= -MAXPOS) cc = 1;
        else if (Dbase >= MAXPOS)  cc = 2;
        const bool skip = (cc != 0) && (cst[jt & 1] == cc);
        if (!skip) stage_rel(Dbase);
        cst[jt & 1] = cc;
        asm volatile("cp.async.commit_group;" ::: "memory");
        // group B: V
#pragma unroll
        for (int i = 0; i < 4; i++) {
            int id = tid + i * 128;
            int r = id >> 3, c = id & 7;
            uint32_t d = sw128(r * 128 + c * 16);
            cp16(sb + A_V + d, g_vf + hb + (size_t)(j0 + r) * DH + c * 8);
        }
        asm volatile("cp.async.commit_group;" ::: "memory");

        asm volatile("cp.async.wait_group 1;" ::: "memory");
        __syncthreads();

        // ---- new S2 columns (64) ----
        if (!skip) s2_group((jt & 1) ? 64 : 0);
        __syncwarp();

        // ---- S1 = Q @ K^T (64x64), single pass ----
        float s[8][4];
#pragma unroll
        for (int nt = 0; nt < 8; nt++)
#pragma unroll
            for (int e = 0; e < 4; e++) s[nt][e] = 0.f;
#pragma unroll
        for (int ks = 0; ks < 4; ks++) {
            uint32_t kb[4][4];
#pragma unroll
            for (int g = 0; g < 4; g++) {
                uint32_t off = sw128((g * 16 + (lane & 15)) * 128
                                     + ks * 32 + (lane >> 4) * 16);
                ldm_x4(sb + A_K + off, kb[g][0], kb[g][1], kb[g][2], kb[g][3]);
            }
#pragma unroll
            for (int nt = 0; nt < 8; nt++) {
                const int p = nt >> 1, s_ = nt & 1;
                mma16816h(s[nt], qa[ks], kb[p][s_], kb[p][s_ + 2]);
            }
        }

        // ---- gather rel bias from ring, online softmax (base-2 domain) ----
        const int rl0 = wbase + (lane >> 2);
#pragma unroll
        for (int nt = 0; nt < 8; nt++)
#pragma unroll
            for (int e = 0; e < 4; e++) {
                const int rr = rl0 + 8 * (e >> 1);
                const int jj = nt * 8 + 2 * (lane & 3) + (e & 1);
                const int slot = (rr - jj + 63 - j0) & 127;
                s[nt][e] += __half2float(s2h[rr * S2S + slot]);
            }

        float mx[2] = {-1e30f, -1e30f};
#pragma unroll
        for (int nt = 0; nt < 8; nt++)
#pragma unroll
            for (int e = 0; e < 4; e++)
                mx[e >> 1] = fmaxf(mx[e >> 1], s[nt][e]);
#pragma unroll
        for (int h2 = 0; h2 < 2; h2++) {
            mx[h2] = fmaxf(mx[h2], __shfl_xor_sync(0xffffffffu, mx[h2], 1));
            mx[h2] = fmaxf(mx[h2], __shfl_xor_sync(0xffffffffu, mx[h2], 2));
        }
        float al2[2];
#pragma unroll
        for (int h2 = 0; h2 < 2; h2++) {
            float mnew = fmaxf(m2[h2], mx[h2]);
            al2[h2] = exp2f(m2[h2] - mnew);
            m2[h2] = mnew;
        }
        float sum[2] = {0.f, 0.f};
#pragma unroll
        for (int nt = 0; nt < 8; nt++)
#pragma unroll
            for (int e = 0; e < 4; e++) {
                float p = exp2f(s[nt][e] - m2[e >> 1]);
                s[nt][e] = p;
                sum[e >> 1] += p;
            }
#pragma unroll
        for (int h2 = 0; h2 < 2; h2++) {
            sum[h2] += __shfl_xor_sync(0xffffffffu, sum[h2], 1);
            sum[h2] += __shfl_xor_sync(0xffffffffu, sum[h2], 2);
            l2[h2] = l2[h2] * al2[h2] + sum[h2];
        }
#pragma unroll
        for (int nt = 0; nt < 8; nt++) {
            o[nt][0] *= al2[0]; o[nt][1] *= al2[0];
            o[nt][2] *= al2[1]; o[nt][3] *= al2[1];
        }

        // ---- P c-frag -> a-frag (single fp16) ----
        uint32_t pa[4][4];
#pragma unroll
        for (int ks = 0; ks < 4; ks++) {
            pa[ks][0] = pack_h2(s[2*ks][0],   s[2*ks][1]);
            pa[ks][1] = pack_h2(s[2*ks][2],   s[2*ks][3]);
            pa[ks][2] = pack_h2(s[2*ks+1][0], s[2*ks+1][1]);
            pa[ks][3] = pack_h2(s[2*ks+1][2], s[2*ks+1][3]);
        }

        asm volatile("cp.async.wait_group 0;" ::: "memory");
        __syncthreads();

        // ---- O += P @ V (single pass) ----
#pragma unroll
        for (int ks = 0; ks < 4; ks++) {
            uint32_t vb[4][4];
            const int jr = ks * 16 + (lane & 7) + ((lane >> 3) & 1) * 8;
#pragma unroll
            for (int dp = 0; dp < 4; dp++) {
                uint32_t off = sw128(jr * 128 + dp * 32 + (lane >> 4) * 16);
                ldm_x4t(sb + A_V + off, vb[dp][0], vb[dp][1], vb[dp][2], vb[dp][3]);
            }
#pragma unroll
            for (int nt = 0; nt < 8; nt++) {
                const int dp = nt >> 1, s_ = (nt & 1) * 2;
                mma16816h(o[nt], pa[ks], vb[dp][s_], vb[dp][s_ + 1]);
            }
        }
    }

    // ---- epilogue: normalize -> single fp16 g_of ----
    const float inv0 = 1.f / l2[0], inv1 = 1.f / l2[1];
    const int row0 = i0 + wbase + (lane >> 2);
#pragma unroll
    for (int nt = 0; nt < 8; nt++) {
        const int d = nt * 8 + 2 * (lane & 3);
        size_t base0 = ((size_t)b * N_SEQ + row0) * INNER + h * DH + d;
        *(uint32_t*)&g_of[base0] = pack_h2(o[nt][0] * inv0, o[nt][1] * inv0);
        size_t base1 = ((size_t)b * N_SEQ + row0 + 8) * INNER + h * DH + d;
        *(uint32_t*)&g_of[base1] = pack_h2(o[nt][2] * inv1, o[nt][3] * inv1);
    }
}

// ---------------------------------------------------------------------------
extern "C" void kernel_launch(void* const* d_in, const int* in_sizes, int n_in,
                              void* d_out, int out_size)
{
    (void)in_sizes; (void)n_in; (void)out_size;
    const float* x   = (const float*)d_in[0];
    const float* Wq  = (const float*)d_in[1];
    const float* Wkv = (const float*)d_in[2];
    const float* Wo  = (const float*)d_in[3];
    const float* bo  = (const float*)d_in[4];
    const float* rel = (const float*)d_in[5];
    float* out = (float*)d_out;

    const int GEMM_SMEM = NSTAGE * STAGE_B;      // 49152
    cudaFuncSetAttribute(gemm_mma, cudaFuncAttributeMaxDynamicSharedMemorySize, GEMM_SMEM);
    cudaFuncSetAttribute(attn_mma, cudaFuncAttributeMaxDynamicSharedMemorySize, ATT_SMEM);

    // all fp32 -> fp16 conversions in one launch (no lo-planes for Wq/Wkv)
    convert_all<<<4096 + NCONV_BLK, 256>>>(x, rel, Wq, Wkv, Wo);

    // fused q/k/v projection: x @ [Wq|Wkv], single-pass (grid 48 x 32)
    gemm_mma<<<dim3(3 * INNER / 64, (B_DIM * N_SEQ) / 64), 128, GEMM_SMEM>>>(0, nullptr, nullptr);

    // fused attention (all-fp16, occ 3 — proven config)
    attn_mma<<<dim3(16, HEADS, B_DIM), 128, ATT_SMEM>>>();

    // out = o @ Wo + bo (2-pass, grid 16 x 32)
    gemm_mma<<<dim3(DIMX / 64, (B_DIM * N_SEQ) / 64), 128, GEMM_SMEM>>>(2, bo, out);
}

// round 17
// speedup vs baseline: 1.0516x; 1.0155x over previous
#include <cuda_runtime.h>
#include <cuda_fp16.h>
#include <cstdint>

#define B_DIM  2
#define N_SEQ  1024
#define DIMX   1024
#define HEADS  16
#define DH     64
#define INNER  1024
#define MAXPOS 512

// ------------------------- device scratch (no allocs) -----------------------
__device__ __align__(16) __half g_xf[(size_t)B_DIM*N_SEQ*DIMX];
__device__ __align__(16) __half g_wph[(size_t)3*DIMX*INNER];   // [Wq|Wkv]^T hi only
__device__ __align__(16) __half g_woh[(size_t)INNER*DIMX];
__device__ __align__(16) __half g_wol[(size_t)INNER*DIMX];
__device__ __align__(16) __half g_of[(size_t)B_DIM*N_SEQ*INNER];
// attention operands all single fp16; q pre-scaled by 0.125*log2e
__device__ __align__(16) __half g_qf[(size_t)B_DIM*HEADS*N_SEQ*DH];
__device__ __align__(16) __half g_kf[(size_t)B_DIM*HEADS*N_SEQ*DH];
__device__ __align__(16) __half g_vf[(size_t)B_DIM*HEADS*N_SEQ*DH];
__device__ __align__(16) __half g_relf[(size_t)(2*MAXPOS+1)*DH];

// ------------------------------- helpers ------------------------------------
__device__ __forceinline__ uint32_t smem_u32(const void* p) {
    uint32_t a;
    asm("{ .reg .u64 t; cvta.to.shared.u64 t, %1; cvt.u32.u64 %0, t; }"
        : "=r"(a) : "l"(p));
    return a;
}
__device__ __forceinline__ void cp16(uint32_t saddr, const void* gaddr) {
    asm volatile("cp.async.cg.shared.global [%0], [%1], 16;"
                 :: "r"(saddr), "l"(gaddr) : "memory");
}
__device__ __forceinline__ void ldm_x4(uint32_t a, uint32_t& r0, uint32_t& r1,
                                       uint32_t& r2, uint32_t& r3) {
    asm volatile("ldmatrix.sync.aligned.m8n8.x4.shared.b16 {%0,%1,%2,%3}, [%4];"
                 : "=r"(r0), "=r"(r1), "=r"(r2), "=r"(r3) : "r"(a));
}
__device__ __forceinline__ void ldm_x4t(uint32_t a, uint32_t& r0, uint32_t& r1,
                                        uint32_t& r2, uint32_t& r3) {
    asm volatile("ldmatrix.sync.aligned.m8n8.x4.trans.shared.b16 {%0,%1,%2,%3}, [%4];"
                 : "=r"(r0), "=r"(r1), "=r"(r2), "=r"(r3) : "r"(a));
}
__device__ __forceinline__ void mma16816h(float* c, const uint32_t* a,
                                          uint32_t b0, uint32_t b1) {
    asm volatile(
        "mma.sync.aligned.m16n8k16.row.col.f32.f16.f16.f32 "
        "{%0,%1,%2,%3}, {%4,%5,%6,%7}, {%8,%9}, {%0,%1,%2,%3};"
        : "+f"(c[0]), "+f"(c[1]), "+f"(c[2]), "+f"(c[3])
        : "r"(a[0]), "r"(a[1]), "r"(a[2]), "r"(a[3]), "r"(b0), "r"(b1));
}
__device__ __forceinline__ uint32_t sw128(uint32_t off) {
    return off ^ ((off >> 3) & 0x70);
}
__device__ __forceinline__ uint32_t pack_h2(float a, float b) {
    __half2 h = __floats2half2_rn(a, b);
    return *(uint32_t*)&h;
}

// ------------------- fused conversion kernel (one launch) -------------------
#define NX4 (B_DIM * N_SEQ * DIMX / 4)          // 524288
#define NR4 ((2 * MAXPOS + 1) * DH / 4)         // 16400
#define NCONV_BLK ((NX4 + NR4 + 255) / 256)     // 2113

__global__ __launch_bounds__(256) void convert_all(const float* __restrict__ x,
                                                   const float* __restrict__ rel,
                                                   const float* __restrict__ Wq,
                                                   const float* __restrict__ Wkv,
                                                   const float* __restrict__ Wo)
{
    const int bid = blockIdx.x;
    if (bid >= 4096) {
        int i = (bid - 4096) * 256 + threadIdx.x;
        if (i >= NX4 + NR4) return;
        if (i < NX4) {
            float4 v = ((const float4*)x)[i];
            ((uint32_t*)g_xf)[2*i]   = pack_h2(v.x, v.y);
            ((uint32_t*)g_xf)[2*i+1] = pack_h2(v.z, v.w);
        } else {
            int j = i - NX4;
            float4 v = ((const float4*)rel)[j];
            ((uint32_t*)g_relf)[2*j]   = pack_h2(v.x, v.y);
            ((uint32_t*)g_relf)[2*j+1] = pack_h2(v.z, v.w);
        }
        return;
    }
    __shared__ float t[32][33];
    const float* W; __half *th, *tl;
    int N, kt, ntile, rowoff;
    bool wantlo;
    if (bid < 1024)      { W = Wq;  N = 1024; kt = bid >> 5; ntile = bid & 31;
                           th = g_wph; tl = nullptr; rowoff = 0; wantlo = false; }
    else if (bid < 3072) { int l = bid - 1024; W = Wkv; N = 2048;
                           kt = l >> 6; ntile = l & 63;
                           th = g_wph; tl = nullptr; rowoff = 1024; wantlo = false; }
    else                 { int l = bid - 3072; W = Wo; N = 1024;
                           kt = l >> 5; ntile = l & 31;
                           th = g_woh; tl = g_wol; rowoff = 0; wantlo = true; }
    const int n0 = ntile * 32, k0 = kt * 32;
    const int tx = threadIdx.x & 31, ty = threadIdx.x >> 5;
#pragma unroll
    for (int r = 0; r < 4; r++)
        t[ty + 8*r][tx] = W[(size_t)(k0 + ty + 8*r) * N + n0 + tx];
    __syncthreads();
#pragma unroll
    for (int r = 0; r < 4; r++) {
        float v = t[tx][ty + 8*r];
        __half h = __float2half_rn(v);
        size_t o = (size_t)(rowoff + n0 + ty + 8*r) * 1024 + k0 + tx;
        th[o] = h;
        if (wantlo) tl[o] = __float2half_rn(v - __half2float(h));
    }
}

// ------------------------- fp16 GEMM (mma.sync) -----------------------------
// Tile 64x64, 128 threads = 4 warps (2x2), warp tile 32x32, BK=64, SW128,
// 2-stage pipeline, occ 4.  (R16 proven config)
#define BK 64
#define A_TILE_B 8192             // 64 rows * 128 B
#define B_TILE_B 8192             // 64 rows * 128 B
#define STAGE_B (A_TILE_B + 2 * B_TILE_B)   // 24576
#define NSTAGE 2

__global__ __launch_bounds__(128, 4) void gemm_mma(int mode,
                                                   const float* __restrict__ bias,
                                                   float* __restrict__ outp)
{
    extern __shared__ __align__(128) char smem[];
    const uint32_t sb = smem_u32(smem);
    const int tid = threadIdx.x;
    const int wid = tid >> 5, lane = tid & 31;
    const int warp_m = wid & 1, warp_n = wid >> 1;   // 2 x 2
    const int m0 = blockIdx.y * 64, n0 = blockIdx.x * 64;
    const bool lite = (mode == 0);

    const __half *A, *Bh, *Bl;
    if (mode == 0) { A = g_xf; Bh = g_wph; Bl = nullptr; }
    else           { A = g_of; Bh = g_woh; Bl = g_wol; }

    float acc[2][4][4];
#pragma unroll
    for (int i = 0; i < 2; i++)
#pragma unroll
        for (int j = 0; j < 4; j++)
#pragma unroll
            for (int t = 0; t < 4; t++) acc[i][j][t] = 0.f;

    const int nkt = DIMX / BK;     // 16

    auto issue_stage = [&](int kt) {
        const int k0 = kt * BK;
        const uint32_t st = sb + (kt & 1) * STAGE_B;
#pragma unroll
        for (int i = 0; i < 4; i++) {
            int id = tid + i * 128;
            int r = id >> 3, cc = id & 7;
            cp16(st + sw128(r * 128 + cc * 16),
                 A + (size_t)(m0 + r) * DIMX + k0 + cc * 8);
        }
#pragma unroll
        for (int i = 0; i < 4; i++) {
            int id = tid + i * 128;
            int r = id >> 3, cc = id & 7;
            uint32_t sw = sw128(r * 128 + cc * 16);
            size_t g = (size_t)(n0 + r) * DIMX + k0 + cc * 8;
            cp16(st + A_TILE_B + sw, Bh + g);
            if (!lite) cp16(st + A_TILE_B + B_TILE_B + sw, Bl + g);
        }
        asm volatile("cp.async.commit_group;" ::: "memory");
    };

    issue_stage(0);

    const int lr = lane & 15;
    const int lcb = (lane >> 4) * 16;

    for (int kt = 0; kt < nkt; kt++) {
        if (kt + 1 < nkt) {
            issue_stage(kt + 1);
            asm volatile("cp.async.wait_group 1;" ::: "memory");
        } else {
            asm volatile("cp.async.wait_group 0;" ::: "memory");
        }
        __syncthreads();

        const uint32_t st = sb + (kt & 1) * STAGE_B;

#pragma unroll
        for (int ks = 0; ks < 4; ks++) {
            const uint32_t koffb = ks * 32 + lcb;
            uint32_t ah[2][4], bh[2][4], bl[2][4];
#pragma unroll
            for (int mt = 0; mt < 2; mt++) {
                uint32_t off = sw128((warp_m * 32 + mt * 16 + lr) * 128 + koffb);
                ldm_x4(st + off, ah[mt][0], ah[mt][1], ah[mt][2], ah[mt][3]);
            }
#pragma unroll
            for (int p = 0; p < 2; p++) {
                uint32_t off = sw128((warp_n * 32 + p * 16 + lr) * 128 + koffb);
                ldm_x4(st + A_TILE_B + off,
                       bh[p][0], bh[p][1], bh[p][2], bh[p][3]);
                if (!lite)
                    ldm_x4(st + A_TILE_B + B_TILE_B + off,
                           bl[p][0], bl[p][1], bl[p][2], bl[p][3]);
            }
#pragma unroll
            for (int mt = 0; mt < 2; mt++)
#pragma unroll
                for (int nt = 0; nt < 4; nt++) {
                    const int p = nt >> 1, s = nt & 1;
                    mma16816h(acc[mt][nt], ah[mt], bh[p][s], bh[p][s + 2]);
                    if (!lite)
                        mma16816h(acc[mt][nt], ah[mt], bl[p][s], bl[p][s + 2]);
                }
        }
        __syncthreads();
    }

    const float qscale = 0.125f * 1.4426950408889634f;
#pragma unroll
    for (int mt = 0; mt < 2; mt++) {
#pragma unroll
        for (int half = 0; half < 2; half++) {
            const int m = m0 + warp_m * 32 + mt * 16 + (lane >> 2) + half * 8;
#pragma unroll
            for (int nt = 0; nt < 4; nt++) {
                const int c = n0 + warp_n * 32 + nt * 8 + 2 * (lane & 3);
                float v0 = acc[mt][nt][half * 2 + 0];
                float v1 = acc[mt][nt][half * 2 + 1];
                if (mode != 0) {
                    float2 o = {v0 + bias[c], v1 + bias[c + 1]};
                    *(float2*)&outp[(size_t)m * DIMX + c] = o;
                } else {
                    const int bb = m >> 10, ii = m & 1023;
                    int col0 = c;
                    __half* dst;
                    float sc = 1.f;
                    if (c < INNER) { dst = g_qf; sc = qscale; }
                    else if (c < 2 * INNER) { dst = g_kf; col0 = c - INNER; }
                    else { dst = g_vf; col0 = c - 2 * INNER; }
                    const int hh = col0 >> 6, dd = col0 & 63;
                    size_t o = (((size_t)bb * HEADS + hh) * N_SEQ + ii) * DH + dd;
                    *(uint32_t*)&dst[o] = pack_h2(v0 * sc, v1 * sc);
                }
            }
        }
    }
}

// ---------------------------------------------------------------------------
// Tensor-core flash attention: all-fp16 operands, fp16 S2 ring, exp2 softmax,
// tri-state clip-skip, occ 3.
// Round-17: DOUBLE-BUFFERED K/V/R -> ONE __syncthreads per j-tile; next-tile
// loads stream into the opposite buffer for a full tile of latency cover.
// ---------------------------------------------------------------------------
#define A_Q   0
#define A_K0  8192
#define A_V0  24576
#define A_R0  40960
#define A_S2  57344
#define S2S   132
#define ATT_SMEM (A_S2 + 64 * S2S * 2)   // 74240

__global__ __launch_bounds__(128, 3) void attn_mma(void)
{
    extern __shared__ __align__(128) char smem[];
    const uint32_t sb = smem_u32(smem);
    __half* s2h = (__half*)(smem + A_S2);

    const int tid  = threadIdx.x;
    const int lane = tid & 31, warp = tid >> 5;
    const int wbase = warp * 16;
    const int i0 = blockIdx.x * 64;
    const int h  = blockIdx.y;
    const int b  = blockIdx.z;
    const size_t hb = ((size_t)b * HEADS + h) * N_SEQ * DH;

    // ---- load Q (single plane) ----
#pragma unroll
    for (int i = 0; i < 4; i++) {
        int id = tid + i * 128;
        int r = id >> 3, c = id & 7;
        uint32_t d = sw128(r * 128 + c * 16);
        cp16(sb + A_Q + d, g_qf + hb + (size_t)(i0 + r) * DH + c * 8);
    }
    asm volatile("cp.async.commit_group;" ::: "memory");
    asm volatile("cp.async.wait_group 0;" ::: "memory");
    __syncthreads();

    uint32_t qa[4][4];
#pragma unroll
    for (int ks = 0; ks < 4; ks++) {
        uint32_t off = sw128((wbase + (lane & 15)) * 128 + ks * 32 + (lane >> 4) * 16);
        ldm_x4(sb + A_Q + off, qa[ks][0], qa[ks][1], qa[ks][2], qa[ks][3]);
    }

    auto stage_rel = [&](int Dbase, int buf) {
        const uint32_t base = sb + A_R0 + buf * 8192;
#pragma unroll
        for (int i = 0; i < 4; i++) {
            int id = tid + i * 128;
            int r = id >> 3, c = id & 7;
            int dist = min(max(Dbase + r, -MAXPOS), MAXPOS) + MAXPOS;
            cp16(base + sw128(r * 128 + c * 16), g_relf + (size_t)dist * DH + c * 8);
        }
    };

    auto s2_group = [&](int baseSlot, int buf) {
        const uint32_t base = sb + A_R0 + buf * 8192;
        float s2[8][4];
#pragma unroll
        for (int nt = 0; nt < 8; nt++)
#pragma unroll
            for (int e = 0; e < 4; e++) s2[nt][e] = 0.f;
#pragma unroll
        for (int ks = 0; ks < 4; ks++) {
            uint32_t rb[4][4];
#pragma unroll
            for (int g = 0; g < 4; g++) {
                uint32_t off = sw128((g * 16 + (lane & 15)) * 128
                                     + ks * 32 + (lane >> 4) * 16);
                ldm_x4(base + off, rb[g][0], rb[g][1], rb[g][2], rb[g][3]);
            }
#pragma unroll
            for (int nt = 0; nt < 8; nt++) {
                const int p = nt >> 1, s_ = nt & 1;
                mma16816h(s2[nt], qa[ks], rb[p][s_], rb[p][s_ + 2]);
            }
        }
        const int rl0 = wbase + (lane >> 2);
#pragma unroll
        for (int nt = 0; nt < 8; nt++) {
            const int col = baseSlot + nt * 8 + 2 * (lane & 3);
            *(uint32_t*)&s2h[rl0 * S2S + col]       = pack_h2(s2[nt][0], s2[nt][1]);
            *(uint32_t*)&s2h[(rl0 + 8) * S2S + col] = pack_h2(s2[nt][2], s2[nt][3]);
        }
    };

    // clip state per R-buffer (parity = jt&1): 0=varying, 1=low const, 2=high const
    int cst[2];
    cst[0] = 0;
    cst[1] = (i0 + 1 >= MAXPOS) ? 2 : 0;

    // ---- pre-group rel rows (dists [i0+1, i0+64]) staged into R buf 1 ----
    stage_rel(i0 + 1, 1);
    asm volatile("cp.async.commit_group;" ::: "memory");
    asm volatile("cp.async.wait_group 0;" ::: "memory");
    __syncthreads();

    // issue tile-0 loads (K/R -> buf0, V -> buf0), one group
    auto issue_tile = [&](int jt) -> bool {
        const int j0 = jt * 64;
        const int buf = jt & 1;
        const uint32_t kb = sb + A_K0 + buf * 8192;
        const uint32_t vb = sb + A_V0 + buf * 8192;
#pragma unroll
        for (int i = 0; i < 4; i++) {
            int id = tid + i * 128;
            int r = id >> 3, c = id & 7;
            uint32_t d = sw128(r * 128 + c * 16);
            size_t g = hb + (size_t)(j0 + r) * DH + c * 8;
            cp16(kb + d, g_kf + g);
            cp16(vb + d, g_vf + g);
        }
        const int Dbase = i0 - j0 - 63;
        int cc = 0;
        if (Dbase + 63 <= -MAXPOS) cc = 1;
        else if (Dbase >= MAXPOS)  cc = 2;
        const bool skip = (cc != 0) && (cst[buf] == cc);
        if (!skip) stage_rel(Dbase, buf);
        cst[buf] = cc;
        asm volatile("cp.async.commit_group;" ::: "memory");
        return skip;
    };

    bool skip_cur = issue_tile(0);

    // pre-group S2 (reads R buf1) overlaps tile-0 loads
    s2_group(64, 1);

    float o[8][4];
#pragma unroll
    for (int nt = 0; nt < 8; nt++)
#pragma unroll
        for (int e = 0; e < 4; e++) o[nt][e] = 0.f;
    float m2[2] = {-1e30f, -1e30f}, l2[2] = {0.f, 0.f};

    for (int jt = 0; jt < 16; jt++) {
        const int j0 = jt * 64;
        const int buf = jt & 1;
        const uint32_t kbuf = sb + A_K0 + buf * 8192;
        const uint32_t vbuf = sb + A_V0 + buf * 8192;

        asm volatile("cp.async.wait_group 0;" ::: "memory");   // tile jt loaded
        __syncthreads();   // publishes buf(jt); retires all reads of buf(jt^1)

        bool skip_next = false;
        if (jt + 1 < 16) skip_next = issue_tile(jt + 1);       // stream into other buf

        // ---- new S2 columns (64) ----
        if (!skip_cur) s2_group((jt & 1) ? 64 : 0, buf);
        __syncwarp();

        // ---- S1 = Q @ K^T (64x64), single pass ----
        float s[8][4];
#pragma unroll
        for (int nt = 0; nt < 8; nt++)
#pragma unroll
            for (int e = 0; e < 4; e++) s[nt][e] = 0.f;
#pragma unroll
        for (int ks = 0; ks < 4; ks++) {
            uint32_t kb[4][4];
#pragma unroll
            for (int g = 0; g < 4; g++) {
                uint32_t off = sw128((g * 16 + (lane & 15)) * 128
                                     + ks * 32 + (lane >> 4) * 16);
                ldm_x4(kbuf + off, kb[g][0], kb[g][1], kb[g][2], kb[g][3]);
            }
#pragma unroll
            for (int nt = 0; nt < 8; nt++) {
                const int p = nt >> 1, s_ = nt & 1;
                mma16816h(s[nt], qa[ks], kb[p][s_], kb[p][s_ + 2]);
            }
        }

        // ---- gather rel bias from ring, online softmax (base-2 domain) ----
        const int rl0 = wbase + (lane >> 2);
#pragma unroll
        for (int nt = 0; nt < 8; nt++)
#pragma unroll
            for (int e = 0; e < 4; e++) {
                const int rr = rl0 + 8 * (e >> 1);
                const int jj = nt * 8 + 2 * (lane & 3) + (e & 1);
                const int slot = (rr - jj + 63 - j0) & 127;
                s[nt][e] += __half2float(s2h[rr * S2S + slot]);
            }

        float mx[2] = {-1e30f, -1e30f};
#pragma unroll
        for (int nt = 0; nt < 8; nt++)
#pragma unroll
            for (int e = 0; e < 4; e++)
                mx[e >> 1] = fmaxf(mx[e >> 1], s[nt][e]);
#pragma unroll
        for (int h2 = 0; h2 < 2; h2++) {
            mx[h2] = fmaxf(mx[h2], __shfl_xor_sync(0xffffffffu, mx[h2], 1));
            mx[h2] = fmaxf(mx[h2], __shfl_xor_sync(0xffffffffu, mx[h2], 2));
        }
        float al2[2];
#pragma unroll
        for (int h2 = 0; h2 < 2; h2++) {
            float mnew = fmaxf(m2[h2], mx[h2]);
            al2[h2] = exp2f(m2[h2] - mnew);
            m2[h2] = mnew;
        }
        float sum[2] = {0.f, 0.f};
#pragma unroll
        for (int nt = 0; nt < 8; nt++)
#pragma unroll
            for (int e = 0; e < 4; e++) {
                float p = exp2f(s[nt][e] - m2[e >> 1]);
                s[nt][e] = p;
                sum[e >> 1] += p;
            }
#pragma unroll
        for (int h2 = 0; h2 < 2; h2++) {
            sum[h2] += __shfl_xor_sync(0xffffffffu, sum[h2], 1);
            sum[h2] += __shfl_xor_sync(0xffffffffu, sum[h2], 2);
            l2[h2] = l2[h2] * al2[h2] + sum[h2];
        }
#pragma unroll
        for (int nt = 0; nt < 8; nt++) {
            o[nt][0] *= al2[0]; o[nt][1] *= al2[0];
            o[nt][2] *= al2[1]; o[nt][3] *= al2[1];
        }

        // ---- P c-frag -> a-frag (single fp16) ----
        uint32_t pa[4][4];
#pragma unroll
        for (int ks = 0; ks < 4; ks++) {
            pa[ks][0] = pack_h2(s[2*ks][0],   s[2*ks][1]);
            pa[ks][1] = pack_h2(s[2*ks][2],   s[2*ks][3]);
            pa[ks][2] = pack_h2(s[2*ks+1][0], s[2*ks+1][1]);
            pa[ks][3] = pack_h2(s[2*ks+1][2], s[2*ks+1][3]);
        }

        // ---- O += P @ V (single pass) ----
#pragma unroll
        for (int ks = 0; ks < 4; ks++) {
            uint32_t vb[4][4];
            const int jr = ks * 16 + (lane & 7) + ((lane >> 3) & 1) * 8;
#pragma unroll
            for (int dp = 0; dp < 4; dp++) {
                uint32_t off = sw128(jr * 128 + dp * 32 + (lane >> 4) * 16);
                ldm_x4t(vbuf + off, vb[dp][0], vb[dp][1], vb[dp][2], vb[dp][3]);
            }
#pragma unroll
            for (int nt = 0; nt < 8; nt++) {
                const int dp = nt >> 1, s_ = (nt & 1) * 2;
                mma16816h(o[nt], pa[ks], vb[dp][s_], vb[dp][s_ + 1]);
            }
        }

        skip_cur = skip_next;
    }

    // ---- epilogue: normalize -> single fp16 g_of ----
    const float inv0 = 1.f / l2[0], inv1 = 1.f / l2[1];
    const int row0 = i0 + wbase + (lane >> 2);
#pragma unroll
    for (int nt = 0; nt < 8; nt++) {
        const int d = nt * 8 + 2 * (lane & 3);
        size_t base0 = ((size_t)b * N_SEQ + row0) * INNER + h * DH + d;
        *(uint32_t*)&g_of[base0] = pack_h2(o[nt][0] * inv0, o[nt][1] * inv0);
        size_t base1 = ((size_t)b * N_SEQ + row0 + 8) * INNER + h * DH + d;
        *(uint32_t*)&g_of[base1] = pack_h2(o[nt][2] * inv1, o[nt][3] * inv1);
    }
}

// ---------------------------------------------------------------------------
extern "C" void kernel_launch(void* const* d_in, const int* in_sizes, int n_in,
                              void* d_out, int out_size)
{
    (void)in_sizes; (void)n_in; (void)out_size;
    const float* x   = (const float*)d_in[0];
    const float* Wq  = (const float*)d_in[1];
    const float* Wkv = (const float*)d_in[2];
    const float* Wo  = (const float*)d_in[3];
    const float* bo  = (const float*)d_in[4];
    const float* rel = (const float*)d_in[5];
    float* out = (float*)d_out;

    const int GEMM_SMEM = NSTAGE * STAGE_B;      // 49152
    cudaFuncSetAttribute(gemm_mma, cudaFuncAttributeMaxDynamicSharedMemorySize, GEMM_SMEM);
    cudaFuncSetAttribute(attn_mma, cudaFuncAttributeMaxDynamicSharedMemorySize, ATT_SMEM);

    // all fp32 -> fp16 conversions in one launch
    convert_all<<<4096 + NCONV_BLK, 256>>>(x, rel, Wq, Wkv, Wo);

    // fused q/k/v projection: x @ [Wq|Wkv], single-pass
    gemm_mma<<<dim3(3 * INNER / 64, (B_DIM * N_SEQ) / 64), 128, GEMM_SMEM>>>(0, nullptr, nullptr);

    // fused attention (double-buffered K/V/R, 1 sync/tile, occ 3)
    attn_mma<<<dim3(16, HEADS, B_DIM), 128, ATT_SMEM>>>();

    // out = o @ Wo + bo (2-pass)
    gemm_mma<<<dim3(DIMX / 64, (B_DIM * N_SEQ) / 64), 128, GEMM_SMEM>>>(2, bo, out);
}